// round 12
// baseline (speedup 1.0000x reference)
#include <cuda_runtime.h>
#include <cuda_fp16.h>
#include <cstdint>
#include <math.h>

#define TOKENS 4096
#define HD 768
#define ID 3072
#define NE 7
#define NA (TOKENS * 2)   // 8192 assignments (top-2)

// ---------------- device scratch (static, no allocation) ----------------
__device__ int   d_counts[NE];
__device__ int   d_offsets[NE + 1];
__device__ int   d_cursor[NE];
__device__ int   d_tkExpert[NA];
__device__ float d_tkProb[NA];
__device__ int   d_rowToken[NA];
__device__ float d_rowProb[NA];
__device__ __align__(16) __half d_x_h[(size_t)TOKENS * HD];      // 6 MB
__device__ __align__(16) __half d_W1s[(size_t)NE * HD * ID];     // 33 MB  [e][k][n]
__device__ __align__(16) __half d_W2s[(size_t)NE * ID * HD];     // 33 MB  [e][k][n]
__device__ __align__(16) __half d_h1[(size_t)NA * ID];           // 50 MB

// ---------------- helpers ----------------
__device__ __forceinline__ void mma16816(float* c, const uint32_t* a,
                                         uint32_t b0, uint32_t b1) {
    asm volatile(
        "mma.sync.aligned.m16n8k16.row.col.f32.f16.f16.f32 "
        "{%0,%1,%2,%3}, {%4,%5,%6,%7}, {%8,%9}, {%0,%1,%2,%3};"
        : "+f"(c[0]), "+f"(c[1]), "+f"(c[2]), "+f"(c[3])
        : "r"(a[0]), "r"(a[1]), "r"(a[2]), "r"(a[3]), "r"(b0), "r"(b1));
}

__device__ __forceinline__ void ldsm4(uint32_t* r, uint32_t addr) {
    asm volatile("ldmatrix.sync.aligned.m8n8.x4.shared.b16 {%0,%1,%2,%3}, [%4];"
                 : "=r"(r[0]), "=r"(r[1]), "=r"(r[2]), "=r"(r[3]) : "r"(addr));
}
__device__ __forceinline__ void ldsm4t(uint32_t* r, uint32_t addr) {
    asm volatile("ldmatrix.sync.aligned.m8n8.x4.trans.shared.b16 {%0,%1,%2,%3}, [%4];"
                 : "=r"(r[0]), "=r"(r[1]), "=r"(r[2]), "=r"(r[3]) : "r"(addr));
}

__device__ __forceinline__ void cpasync16(uint32_t dst, const void* src) {
    asm volatile("cp.async.cg.shared.global [%0], [%1], 16;"
                 :: "r"(dst), "l"(src) : "memory");
}
__device__ __forceinline__ void cp_commit() {
    asm volatile("cp.async.commit_group;" ::: "memory");
}
__device__ __forceinline__ void cp_wait1() {
    asm volatile("cp.async.wait_group 1;" ::: "memory");
}

__device__ __forceinline__ uint32_t pack_h(__half a, __half b) {
    __half2 t; t.x = a; t.y = b;
    uint32_t r; memcpy(&r, &t, 4); return r;
}

// ---------------- small utility kernels ----------------
__global__ void reset_counters_kernel() {
    int i = threadIdx.x;
    if (i < NE) { d_counts[i] = 0; d_cursor[i] = 0; }
}

__global__ void zero_out_kernel(float* out, int n) {
    int i = blockIdx.x * blockDim.x + threadIdx.x;
    if (i < n) out[i] = 0.0f;
}

// vectorized fp32 -> fp16 converters (8 elements per thread)
__device__ __forceinline__ void conv8(const float* __restrict__ src,
                                      __half* __restrict__ dst, size_t i) {
    float4 v0 = *(const float4*)(src + i);
    float4 v1 = *(const float4*)(src + i + 4);
    uint4 o;
    o.x = pack_h(__float2half(v0.x), __float2half(v0.y));
    o.y = pack_h(__float2half(v0.z), __float2half(v0.w));
    o.z = pack_h(__float2half(v1.x), __float2half(v1.y));
    o.w = pack_h(__float2half(v1.z), __float2half(v1.w));
    *(uint4*)(dst + i) = o;
}

__global__ void conv_x_kernel(const float* __restrict__ x) {
    size_t i = ((size_t)blockIdx.x * blockDim.x + threadIdx.x) * 8;
    if (i < (size_t)TOKENS * HD) conv8(x, d_x_h, i);
}
__global__ void conv_w1_kernel(const float* __restrict__ W1) {
    size_t i = ((size_t)blockIdx.x * blockDim.x + threadIdx.x) * 8;
    if (i < (size_t)NE * HD * ID) conv8(W1, d_W1s, i);
}
__global__ void conv_w2_kernel(const float* __restrict__ W2) {
    size_t i = ((size_t)blockIdx.x * blockDim.x + threadIdx.x) * 8;
    if (i < (size_t)NE * ID * HD) conv8(W2, d_W2s, i);
}

// ---------------- gate: logits, top-2 softmax, assignment build ----------------
__global__ void gate_kernel(const float* __restrict__ x,
                            const float* __restrict__ gW,
                            const float* __restrict__ gb,
                            float* __restrict__ out_gw) {
    int t = blockIdx.x;
    __shared__ float logits[NE];
    int w = threadIdx.x >> 5;
    int lane = threadIdx.x & 31;
    const float* xr = x + (size_t)t * HD;
    if (w < NE) {
        const float* wr = gW + (size_t)w * HD;
        float s = 0.0f;
        for (int h = lane; h < HD; h += 32) s += xr[h] * wr[h];
        #pragma unroll
        for (int o = 16; o; o >>= 1) s += __shfl_down_sync(0xffffffffu, s, o);
        if (lane == 0) logits[w] = s + gb[w];
    }
    __syncthreads();
    if (threadIdx.x == 0) {
        int i0 = 0;
        #pragma unroll
        for (int e = 1; e < NE; e++) if (logits[e] > logits[i0]) i0 = e;
        int i1 = -1;
        #pragma unroll
        for (int e = 0; e < NE; e++) {
            if (e == i0) continue;
            if (i1 < 0 || logits[e] > logits[i1]) i1 = e;
        }
        float v0 = logits[i0], v1 = logits[i1];
        float e1 = expf(v1 - v0);
        float inv = 1.0f / (1.0f + e1);
        float p0 = inv, p1 = e1 * inv;
        float* gw = out_gw + (size_t)t * NE;
        #pragma unroll
        for (int e = 0; e < NE; e++) gw[e] = 0.0f;
        gw[i0] = p0; gw[i1] = p1;
        d_tkExpert[t * 2 + 0] = i0; d_tkProb[t * 2 + 0] = p0;
        d_tkExpert[t * 2 + 1] = i1; d_tkProb[t * 2 + 1] = p1;
        atomicAdd(&d_counts[i0], 1);
        atomicAdd(&d_counts[i1], 1);
    }
}

__global__ void offsets_kernel() {
    int acc = 0;
    for (int e = 0; e < NE; e++) { d_offsets[e] = acc; acc += d_counts[e]; }
    d_offsets[NE] = acc;
}

__global__ void scatter_kernel() {
    int a = blockIdx.x * blockDim.x + threadIdx.x;
    if (a >= NA) return;
    int e = d_tkExpert[a];
    int pos = d_offsets[e] + atomicAdd(&d_cursor[e], 1);
    d_rowToken[pos] = a >> 1;
    d_rowProb[pos]  = d_tkProb[a];
}

// ---------------- HMMA mainloop ----------------
// Tile 128(M) x 128(N), k-tile 64, 256 threads = 8 warps (2 M x 4 N),
// warp tile 64x32.  Plain fp16 operands.  Supports a k-range [k0, k0+64*ktiles)
// for split-K.  cp.async 3-stage pipeline, one __syncthreads per k-tile.
// A smem [128][64] fp16: rows 128B = 8 chunks of 16B, phys chunk = c ^ (r&7).
// B smem [64][128] fp16 k-major: rows 256B = 16 chunks, phys = c ^ (k&7).
#define STG_A 0u
#define STG_B 16384u
#define STG_BYTES 32768u
#define NSTAGE 3
#define DSMEM_BYTES (NSTAGE * 32768)   // 96 KB

template<int KDIM>
__device__ __forceinline__ void mainloop(
    const __half* __restrict__ A,     // [rows][KDIM] fp16
    const __half* __restrict__ B,     // [KDIM][NDIM] fp16
    int NDIM, int n0,
    int k0, int ktiles,               // k-range: [k0, k0 + 64*ktiles)
    const int* arow,                  // smem: 128 absolute row indices into A
    uint32_t sm,                      // u32 shared addr of dynamic smem
    float acc[4][4][4])
{
    int tid = threadIdx.x;
    int lane = tid & 31, warp = tid >> 5;
    int warpM = (warp >> 2) * 64;    // 2 M-warps
    int warpN = (warp & 3) * 32;     // 4 N-warps
    int g = lane >> 3;               // ldmatrix group 0..3
    int lr = lane & 7;               // row-in-group

    // ---- cp.async assignments: A 4 chunks, B 4 chunks per thread
    int acr = tid >> 1;              // A row 0..127
    int acb = (tid & 1) * 4;         // chunk base 0 or 4
    const __half* aSrc = A + (size_t)arow[acr] * KDIM + k0 + acb * 8;
    uint32_t aD[4];
    #pragma unroll
    for (int i = 0; i < 4; i++)
        aD[i] = (uint32_t)(acr * 128 + (((acb + i) ^ (acr & 7)) << 4));

    int bkr = tid >> 2;              // B k-row 0..63
    int bcb = (tid & 3) * 4;         // chunk base 0,4,8,12
    const __half* bSrc = B + (size_t)(k0 + bkr) * NDIM + n0 + bcb * 8;
    uint32_t bD[4];
    #pragma unroll
    for (int i = 0; i < 4; i++)
        bD[i] = (uint32_t)(bkr * 256 + (((bcb + i) ^ (bkr & 7)) << 4));

    auto load_stage = [&](int kt) {
        uint32_t sb = sm + (uint32_t)(kt % NSTAGE) * STG_BYTES;
        size_t ako = (size_t)kt * 64;
        size_t bko = (size_t)kt * 64 * NDIM;
        #pragma unroll
        for (int i = 0; i < 4; i++)
            cpasync16(sb + STG_A + aD[i], aSrc + ako + i * 8);
        #pragma unroll
        for (int i = 0; i < 4; i++)
            cpasync16(sb + STG_B + bD[i], bSrc + bko + i * 8);
    };

    auto compute_stage = [&](int s) {
        uint32_t sb = sm + (uint32_t)s * STG_BYTES;
        #pragma unroll
        for (int kk = 0; kk < 4; kk++) {
            uint32_t a[4][4], bh[2][4];
            #pragma unroll
            for (int mi = 0; mi < 4; mi++) {
                int row = warpM + mi * 16 + (g & 1) * 8 + lr;
                int ch = (kk * 2 + (g >> 1)) ^ (row & 7);
                ldsm4(a[mi], sb + STG_A + (uint32_t)(row * 128 + ch * 16));
            }
            #pragma unroll
            for (int nh = 0; nh < 2; nh++) {
                int k = kk * 16 + (g & 1) * 8 + lr;
                int n = warpN + nh * 16 + (g >> 1) * 8;
                int ch = (n >> 3) ^ (k & 7);
                ldsm4t(bh[nh], sb + STG_B + (uint32_t)(k * 256 + ch * 16));
            }
            #pragma unroll
            for (int mi = 0; mi < 4; mi++) {
                #pragma unroll
                for (int j = 0; j < 4; j++) {
                    int nh = j >> 1, o = (j & 1) * 2;
                    mma16816(acc[mi][j], a[mi], bh[nh][o], bh[nh][o + 1]);
                }
            }
        }
    };

    load_stage(0); cp_commit();
    load_stage(1); cp_commit();

    for (int kt = 0; kt < ktiles; kt++) {
        cp_wait1();              // stage kt arrived
        __syncthreads();         // ...and stage slot (kt+2)%3 fully consumed
        if (kt + 2 < ktiles) load_stage(kt + 2);
        cp_commit();
        compute_stage(kt % NSTAGE);
    }
}

// ===================== GEMM1: h1 = gelu(x @ W1 + b1) ==========================
__global__ void __launch_bounds__(256, 2)
gemm1_hmma(const float* __restrict__ b1) {
    int e = blockIdx.z;
    int cnt = d_counts[e];
    int rowTile = blockIdx.y * 128;
    if (rowTile >= cnt) return;
    int base = d_offsets[e];
    int n0 = blockIdx.x * 128;

    extern __shared__ __align__(16) char dyn_raw[];
    uint32_t sm = (uint32_t)__cvta_generic_to_shared(dyn_raw);

    __shared__ int arow[128];
    int tid = threadIdx.x;
    if (tid < 128) {
        int r = rowTile + tid;
        arow[tid] = d_rowToken[base + min(r, cnt - 1)];
    }
    __syncthreads();

    float acc[4][4][4] = {};
    mainloop<HD>(d_x_h, d_W1s + (size_t)e * HD * ID,
                 ID, n0, 0, HD / 64, arow, sm, acc);

    int lane = tid & 31, warp = tid >> 5;
    int warpM = (warp >> 2) * 64, warpN = (warp & 3) * 32;
    int qr = lane >> 2, qc = (lane & 3) * 2;
    const float* bb = b1 + (size_t)e * ID;
    #pragma unroll
    for (int mi = 0; mi < 4; mi++) {
        #pragma unroll
        for (int rr = 0; rr < 2; rr++) {
            int lrow = warpM + mi * 16 + rr * 8 + qr;
            int gr = rowTile + lrow;
            if (gr >= cnt) continue;
            size_t orow = (size_t)(base + gr) * ID + n0;
            #pragma unroll
            for (int j = 0; j < 4; j++) {
                int n = warpN + j * 8 + qc;
                float v0 = acc[mi][j][rr * 2]     + bb[n0 + n];
                float v1 = acc[mi][j][rr * 2 + 1] + bb[n0 + n + 1];
                float g0 = 0.5f * v0 * (1.0f + erff(v0 * 0.70710678118654752f));
                float g1 = 0.5f * v1 * (1.0f + erff(v1 * 0.70710678118654752f));
                *(uint32_t*)(d_h1 + orow + n) =
                    pack_h(__float2half(g0), __float2half(g1));
            }
        }
    }
}

// ===================== GEMM2: out += p * (h1 @ W2 + b2), split-K x2 ===========
__global__ void __launch_bounds__(256, 2)
gemm2_hmma(const float* __restrict__ b2, float* __restrict__ out) {
    int ez = blockIdx.z;
    int e = ez % NE;
    int split = ez / NE;               // 0 or 1
    int cnt = d_counts[e];
    int rowTile = blockIdx.y * 128;
    if (rowTile >= cnt) return;
    int base = d_offsets[e];
    int n0 = blockIdx.x * 128;
    int k0 = split * (ID / 2);

    extern __shared__ __align__(16) char dyn_raw[];
    uint32_t sm = (uint32_t)__cvta_generic_to_shared(dyn_raw);

    __shared__ int arow[128];
    __shared__ int stok[128];
    __shared__ float sprob[128];
    int tid = threadIdx.x;
    if (tid < 128) {
        int r = rowTile + tid;
        int rc = base + min(r, cnt - 1);
        arow[tid]  = rc;
        stok[tid]  = d_rowToken[rc];
        sprob[tid] = d_rowProb[rc];
    }
    __syncthreads();

    float acc[4][4][4] = {};
    mainloop<ID>(d_h1, d_W2s + (size_t)e * ID * HD,
                 HD, n0, k0, (ID / 2) / 64, arow, sm, acc);

    int lane = tid & 31, warp = tid >> 5;
    int warpM = (warp >> 2) * 64, warpN = (warp & 3) * 32;
    int qr = lane >> 2, qc = (lane & 3) * 2;
    const float* bb = b2 + (size_t)e * HD;
    float bscale = (split == 0) ? 1.0f : 0.0f;
    #pragma unroll
    for (int mi = 0; mi < 4; mi++) {
        #pragma unroll
        for (int rr = 0; rr < 2; rr++) {
            int lrow = warpM + mi * 16 + rr * 8 + qr;
            int gr = rowTile + lrow;
            if (gr >= cnt) continue;
            int tok = stok[lrow];
            float p = sprob[lrow];
            float* od = out + (size_t)tok * HD + n0;
            #pragma unroll
            for (int j = 0; j < 4; j++) {
                int n = warpN + j * 8 + qc;
                atomicAdd(&od[n],
                          p * (acc[mi][j][rr * 2]     + bscale * bb[n0 + n]));
                atomicAdd(&od[n + 1],
                          p * (acc[mi][j][rr * 2 + 1] + bscale * bb[n0 + n + 1]));
            }
        }
    }
}

// ---------------- launch ----------------
extern "C" void kernel_launch(void* const* d_in, const int* in_sizes, int n_in,
                              void* d_out, int out_size) {
    const float* x     = (const float*)d_in[0];
    const float* gateW = (const float*)d_in[1];
    const float* gateB = (const float*)d_in[2];
    const float* W1    = (const float*)d_in[3];
    const float* b1    = (const float*)d_in[4];
    const float* W2    = (const float*)d_in[5];
    const float* b2    = (const float*)d_in[6];
    float* out = (float*)d_out;                    // [TOKENS*HD]
    float* out_gw = out + (size_t)TOKENS * HD;     // [TOKENS*NE]

    cudaFuncSetAttribute(gemm1_hmma, cudaFuncAttributeMaxDynamicSharedMemorySize, DSMEM_BYTES);
    cudaFuncSetAttribute(gemm2_hmma, cudaFuncAttributeMaxDynamicSharedMemorySize, DSMEM_BYTES);

    reset_counters_kernel<<<1, 32>>>();
    zero_out_kernel<<<(TOKENS * HD + 255) / 256, 256>>>(out, TOKENS * HD);
    gate_kernel<<<TOKENS, 224>>>(x, gateW, gateB, out_gw);
    offsets_kernel<<<1, 1>>>();
    scatter_kernel<<<(NA + 255) / 256, 256>>>();
    conv_x_kernel<<<(TOKENS * HD / 8 + 255) / 256, 256>>>(x);
    {
        size_t nw = (size_t)NE * HD * ID;
        int blocks = (int)((nw / 8 + 255) / 256);
        conv_w1_kernel<<<blocks, 256>>>(W1);
        conv_w2_kernel<<<blocks, 256>>>(W2);
    }

    dim3 g1(ID / 128, NA / 128, NE);       // (24, 64, 7)
    gemm1_hmma<<<g1, 256, DSMEM_BYTES>>>(b1);

    dim3 g2(HD / 128, NA / 128, NE * 2);   // (6, 64, 14)  split-K x2
    gemm2_hmma<<<g2, 256, DSMEM_BYTES>>>(b2, out);
}